// round 1
// baseline (speedup 1.0000x reference)
#include <cuda_runtime.h>
#include <cstdint>

#define B_     8
#define S_     1024
#define D_     512
#define H_     8
#define HD_    64
#define FF_    2048
#define STEPS_ 64
#define CAP_   1088
#define MTOK   (B_*S_)   /* 8192 */

// ---------------- device scratch (no cudaMalloc allowed) ----------------
__device__ float g_qkv [MTOK*1536];   // prefill QKV
__device__ float g_attn[MTOK*D_];     // prefill attention output
__device__ float g_pre [MTOK*D_];     // pre-LN buffer
__device__ float g_h   [MTOK*D_];     // post-LN1 hidden
__device__ float g_hff [MTOK*FF_];    // MLP hidden
__device__ float g_kc  [B_*CAP_*D_];  // K cache
__device__ float g_vc  [B_*CAP_*D_];  // V cache
__device__ float g_qt  [B_*D_];       // decode q
__device__ float g_at  [B_*D_];       // decode attn out
__device__ float g_ht  [B_*D_];       // decode post-LN1
__device__ float g_hfft[B_*FF_];      // decode MLP hidden
__device__ float g_t1  [B_*D_];       // decode temp

// ---------------- reductions ----------------
__device__ __forceinline__ float warpRedSum(float v) {
#pragma unroll
    for (int o = 16; o; o >>= 1) v += __shfl_xor_sync(0xffffffffu, v, o);
    return v;
}
__device__ __forceinline__ float warpRedMax(float v) {
#pragma unroll
    for (int o = 16; o; o >>= 1) v = fmaxf(v, __shfl_xor_sync(0xffffffffu, v, o));
    return v;
}

// ---------------- SGEMM (NT): C[m,n] = sum_k A[m,k]*B[n,k] (+bias,+res,relu) ----------------
// BM=BN=128, BK=16, 256 threads, 8x8 per thread.
template<int BIAS, int RELU, int RES>
__global__ void __launch_bounds__(256) sgemm_nt(
    const float* __restrict__ A, const float* __restrict__ Bm,
    const float* __restrict__ bias, const float* __restrict__ R,
    float* __restrict__ C, int M, int N, int K)
{
    __shared__ float As[16][132];
    __shared__ float Bs[16][132];
    const int tid = threadIdx.x;
    const int m0 = blockIdx.y * 128;
    const int n0 = blockIdx.x * 128;
    const int tx = tid & 15, ty = tid >> 4;
    const int r0 = ty * 8, c0 = tx * 8;
    const int lrow = tid >> 2;       // 0..63
    const int lk4  = (tid & 3) * 4;  // 0,4,8,12

    float acc[8][8];
#pragma unroll
    for (int i = 0; i < 8; i++)
#pragma unroll
        for (int j = 0; j < 8; j++) acc[i][j] = 0.f;

    for (int k0 = 0; k0 < K; k0 += 16) {
#pragma unroll
        for (int half = 0; half < 2; half++) {
            int row = lrow + half * 64;
            float4 a = *(const float4*)(A + (size_t)(m0 + row) * K + k0 + lk4);
            As[lk4 + 0][row] = a.x; As[lk4 + 1][row] = a.y;
            As[lk4 + 2][row] = a.z; As[lk4 + 3][row] = a.w;
            float4 b = *(const float4*)(Bm + (size_t)(n0 + row) * K + k0 + lk4);
            Bs[lk4 + 0][row] = b.x; Bs[lk4 + 1][row] = b.y;
            Bs[lk4 + 2][row] = b.z; Bs[lk4 + 3][row] = b.w;
        }
        __syncthreads();
#pragma unroll
        for (int kk = 0; kk < 16; kk++) {
            float af[8], bf[8];
            *(float4*)(af)     = *(const float4*)(&As[kk][r0]);
            *(float4*)(af + 4) = *(const float4*)(&As[kk][r0 + 4]);
            *(float4*)(bf)     = *(const float4*)(&Bs[kk][c0]);
            *(float4*)(bf + 4) = *(const float4*)(&Bs[kk][c0 + 4]);
#pragma unroll
            for (int i = 0; i < 8; i++)
#pragma unroll
                for (int j = 0; j < 8; j++)
                    acc[i][j] = fmaf(af[i], bf[j], acc[i][j]);
        }
        __syncthreads();
    }

    float bl[8];
#pragma unroll
    for (int j = 0; j < 8; j++) bl[j] = BIAS ? bias[n0 + c0 + j] : 0.f;

#pragma unroll
    for (int i = 0; i < 8; i++) {
        size_t rowoff = (size_t)(m0 + r0 + i) * N + n0 + c0;
#pragma unroll
        for (int j4 = 0; j4 < 8; j4 += 4) {
            float t0 = acc[i][j4 + 0] + bl[j4 + 0];
            float t1 = acc[i][j4 + 1] + bl[j4 + 1];
            float t2 = acc[i][j4 + 2] + bl[j4 + 2];
            float t3 = acc[i][j4 + 3] + bl[j4 + 3];
            if (RES) {
                float4 r = *(const float4*)(R + rowoff + j4);
                t0 += r.x; t1 += r.y; t2 += r.z; t3 += r.w;
            }
            if (RELU) {
                t0 = fmaxf(t0, 0.f); t1 = fmaxf(t1, 0.f);
                t2 = fmaxf(t2, 0.f); t3 = fmaxf(t3, 0.f);
            }
            float4 v; v.x = t0; v.y = t1; v.z = t2; v.w = t3;
            *(float4*)(C + rowoff + j4) = v;
        }
    }
}

// ---------------- prefill flash attention (causal), 64x64 tiles ----------------
// grid: (S/64, B*H), 256 threads, dynamic smem = (64*64 + 64*65 + 64*64)*4 = 49408 B
__global__ void __launch_bounds__(256) attn_prefill(const float* __restrict__ qkv,
                                                    float* __restrict__ attn)
{
    extern __shared__ float sm[];
    float* Qs = sm;            // [d][r] pitch 64
    float* KP = sm + 64 * 64;  // K: [d][c] pitch 65; then P: [r][c] pitch 65
    float* Vs = KP + 64 * 65;  // [t][d] pitch 64

    const int b  = blockIdx.y >> 3;
    const int h  = blockIdx.y & 7;
    const int l0 = blockIdx.x * 64;
    const int tid = threadIdx.x;
    const int tx = tid & 15, ty = tid >> 4;
    const int r0 = ty * 4, c0 = tx * 4;

    const size_t rowbase = (size_t)(b * S_) * 1536;
    const float* qbase = qkv + rowbase + h * 64;
    const float* kbase = qkv + rowbase + 512 + h * 64;
    const float* vbase = qkv + rowbase + 1024 + h * 64;

    const int lt  = tid >> 4;        // 0..15
    const int ld4 = (tid & 15) * 4;  // 0..60

#pragma unroll
    for (int tt = lt; tt < 64; tt += 16) {
        float4 q4 = *(const float4*)(qbase + (size_t)(l0 + tt) * 1536 + ld4);
        Qs[(ld4 + 0) * 64 + tt] = q4.x;
        Qs[(ld4 + 1) * 64 + tt] = q4.y;
        Qs[(ld4 + 2) * 64 + tt] = q4.z;
        Qs[(ld4 + 3) * 64 + tt] = q4.w;
    }

    float o[4][4];
    float mrow[4], lrow[4];
#pragma unroll
    for (int i = 0; i < 4; i++) {
        mrow[i] = -1e30f; lrow[i] = 0.f;
#pragma unroll
        for (int j = 0; j < 4; j++) o[i][j] = 0.f;
    }

    const int ntiles = (l0 >> 6) + 1;
    for (int tile = 0; tile < ntiles; ++tile) {
        const int j0 = tile * 64;
        __syncthreads();  // previous phase-2 reads of KP/Vs done
#pragma unroll
        for (int tt = lt; tt < 64; tt += 16) {
            float4 k4 = *(const float4*)(kbase + (size_t)(j0 + tt) * 1536 + ld4);
            KP[(ld4 + 0) * 65 + tt] = k4.x;
            KP[(ld4 + 1) * 65 + tt] = k4.y;
            KP[(ld4 + 2) * 65 + tt] = k4.z;
            KP[(ld4 + 3) * 65 + tt] = k4.w;
            float4 v4 = *(const float4*)(vbase + (size_t)(j0 + tt) * 1536 + ld4);
            *(float4*)(Vs + tt * 64 + ld4) = v4;
        }
        __syncthreads();

        float s[4][4];
#pragma unroll
        for (int i = 0; i < 4; i++)
#pragma unroll
            for (int j = 0; j < 4; j++) s[i][j] = 0.f;

        for (int d = 0; d < 64; d++) {
            float qf[4];
            *(float4*)qf = *(const float4*)(Qs + d * 64 + r0);
            float kf0 = KP[d * 65 + c0 + 0];
            float kf1 = KP[d * 65 + c0 + 1];
            float kf2 = KP[d * 65 + c0 + 2];
            float kf3 = KP[d * 65 + c0 + 3];
#pragma unroll
            for (int i = 0; i < 4; i++) {
                s[i][0] = fmaf(qf[i], kf0, s[i][0]);
                s[i][1] = fmaf(qf[i], kf1, s[i][1]);
                s[i][2] = fmaf(qf[i], kf2, s[i][2]);
                s[i][3] = fmaf(qf[i], kf3, s[i][3]);
            }
        }

        if (j0 == l0) {  // diagonal tile: causal mask
#pragma unroll
            for (int i = 0; i < 4; i++)
#pragma unroll
                for (int j = 0; j < 4; j++)
                    s[i][j] = (j0 + c0 + j > l0 + r0 + i) ? -1e30f : s[i][j] * 0.125f;
        } else {
#pragma unroll
            for (int i = 0; i < 4; i++)
#pragma unroll
                for (int j = 0; j < 4; j++) s[i][j] *= 0.125f;
        }

        float p[4][4];
#pragma unroll
        for (int i = 0; i < 4; i++) {
            float rm = fmaxf(fmaxf(s[i][0], s[i][1]), fmaxf(s[i][2], s[i][3]));
#pragma unroll
            for (int off = 8; off; off >>= 1)
                rm = fmaxf(rm, __shfl_xor_sync(0xffffffffu, rm, off));
            float mnew  = fmaxf(mrow[i], rm);
            float alpha = __expf(mrow[i] - mnew);
            float ps = 0.f;
#pragma unroll
            for (int j = 0; j < 4; j++) { p[i][j] = __expf(s[i][j] - mnew); ps += p[i][j]; }
#pragma unroll
            for (int off = 8; off; off >>= 1)
                ps += __shfl_xor_sync(0xffffffffu, ps, off);
            lrow[i] = lrow[i] * alpha + ps;
            mrow[i] = mnew;
#pragma unroll
            for (int j = 0; j < 4; j++) o[i][j] *= alpha;
        }

        __syncthreads();  // done reading K from KP
#pragma unroll
        for (int i = 0; i < 4; i++)
#pragma unroll
            for (int j = 0; j < 4; j++)
                KP[(r0 + i) * 65 + c0 + j] = p[i][j];
        __syncthreads();

        for (int c = 0; c < 64; c++) {
            float vv[4];
            *(float4*)vv = *(const float4*)(Vs + c * 64 + c0);
            float p0 = KP[(r0 + 0) * 65 + c];
            float p1 = KP[(r0 + 1) * 65 + c];
            float p2 = KP[(r0 + 2) * 65 + c];
            float p3 = KP[(r0 + 3) * 65 + c];
#pragma unroll
            for (int j = 0; j < 4; j++) {
                o[0][j] = fmaf(p0, vv[j], o[0][j]);
                o[1][j] = fmaf(p1, vv[j], o[1][j]);
                o[2][j] = fmaf(p2, vv[j], o[2][j]);
                o[3][j] = fmaf(p3, vv[j], o[3][j]);
            }
        }
    }

    float* ob = attn + (size_t)(b * S_ + l0) * 512 + h * 64;
#pragma unroll
    for (int i = 0; i < 4; i++) {
        float inv = 1.f / lrow[i];
        float4 v;
        v.x = o[i][0] * inv; v.y = o[i][1] * inv;
        v.z = o[i][2] * inv; v.w = o[i][3] * inv;
        *(float4*)(ob + (size_t)(r0 + i) * 512 + c0) = v;
    }
}

// ---------------- copy prefill K/V slices into the caches ----------------
__global__ void __launch_bounds__(128) copy_kv(const float* __restrict__ qkv,
                                               float* __restrict__ kc, float* __restrict__ vc)
{
    const int r = blockIdx.x;            // 0..8191
    const int b = r >> 10, s = r & 1023;
    const int tid = threadIdx.x;         // 0..127
    const float4* src = (const float4*)(qkv + (size_t)r * 1536);
    float4* kd = (float4*)(kc + (size_t)(b * CAP_ + s) * 512);
    float4* vd = (float4*)(vc + (size_t)(b * CAP_ + s) * 512);
    kd[tid] = src[128 + tid];
    vd[tid] = src[256 + tid];
}

// ---------------- prefill LayerNorm over rows of 512 ----------------
// outExtra: output row = r + (r>>10)*outExtra (0 for plain, 64 to remap 1024->1088 stride)
__global__ void __launch_bounds__(256) ln_rows(const float* __restrict__ in,
                                               const float* __restrict__ g,
                                               const float* __restrict__ be,
                                               float* __restrict__ out, int outExtra)
{
    const int r = blockIdx.x;
    const int tid = threadIdx.x;
    const float* row = in + (size_t)r * 512;
    float v0 = row[tid], v1 = row[tid + 256];
    float s  = warpRedSum(v0 + v1);
    float s2 = warpRedSum(v0 * v0 + v1 * v1);
    __shared__ float r1[8], r2[8];
    __shared__ float smu, srs;
    const int w = tid >> 5, lane = tid & 31;
    if (lane == 0) { r1[w] = s; r2[w] = s2; }
    __syncthreads();
    if (tid == 0) {
        float S = 0.f, S2 = 0.f;
#pragma unroll
        for (int i = 0; i < 8; i++) { S += r1[i]; S2 += r2[i]; }
        float mu  = S * (1.f / 512.f);
        float var = S2 * (1.f / 512.f) - mu * mu;
        smu = mu; srs = rsqrtf(var + 1e-5f);
    }
    __syncthreads();
    const int orow = r + (r >> 10) * outExtra;
    float* od = out + (size_t)orow * 512;
    od[tid]       = (v0 - smu) * srs * g[tid]       + be[tid];
    od[tid + 256] = (v1 - smu) * srs * g[tid + 256] + be[tid + 256];
}

// ---------------- decode: QKV GEMV, routes k/v into the caches ----------------
__global__ void __launch_bounds__(256) dec_qkv(const float* __restrict__ xt,
                                               const float* __restrict__ W,
                                               const float* __restrict__ bias,
                                               float* __restrict__ qt,
                                               float* __restrict__ kc,
                                               float* __restrict__ vc, int cur)
{
    __shared__ float xs[512];
    const int b = blockIdx.y;
    const int tid = threadIdx.x;
    const float* xrow = xt + (size_t)b * 512;
    xs[tid] = xrow[tid];
    xs[tid + 256] = xrow[tid + 256];
    __syncthreads();
    const int w = tid >> 5, lane = tid & 31;
    const int e = blockIdx.x * 8 + w;
    const float* wr = W + (size_t)e * 512;
    float acc = 0.f;
#pragma unroll
    for (int k = lane * 4; k < 512; k += 128) {
        float4 wv = *(const float4*)(wr + k);
        float4 xv = *(const float4*)(xs + k);
        acc = fmaf(wv.x, xv.x, fmaf(wv.y, xv.y, fmaf(wv.z, xv.z, fmaf(wv.w, xv.w, acc))));
    }
    acc = warpRedSum(acc);
    if (lane == 0) {
        float rv = acc + bias[e];
        if (e < 512)       qt[b * 512 + e] = rv;
        else if (e < 1024) kc[((size_t)b * CAP_ + cur) * 512 + (e - 512)]  = rv;
        else               vc[((size_t)b * CAP_ + cur) * 512 + (e - 1024)] = rv;
    }
}

// ---------------- decode: generic warp-per-output GEMV ----------------
__global__ void __launch_bounds__(256) dec_gemv(const float* __restrict__ in,
                                                const float* __restrict__ W,
                                                const float* __restrict__ bias,
                                                float* __restrict__ out,
                                                int K, int N, int relu)
{
    __shared__ float xs[2048];
    const int b = blockIdx.y;
    const int tid = threadIdx.x;
    const float* xrow = in + (size_t)b * K;
    for (int k = tid; k < K; k += 256) xs[k] = xrow[k];
    __syncthreads();
    const int w = tid >> 5, lane = tid & 31;
    const int n = blockIdx.x * 8 + w;
    const float* wr = W + (size_t)n * K;
    float acc = 0.f;
    for (int k = lane * 4; k < K; k += 128) {
        float4 wv = *(const float4*)(wr + k);
        float4 xv = *(const float4*)(xs + k);
        acc = fmaf(wv.x, xv.x, fmaf(wv.y, xv.y, fmaf(wv.z, xv.z, fmaf(wv.w, xv.w, acc))));
    }
    acc = warpRedSum(acc);
    if (lane == 0) {
        float rv = acc + bias[n];
        if (relu) rv = fmaxf(rv, 0.f);
        out[(size_t)b * N + n] = rv;
    }
}

// ---------------- decode attention: one block per (h, b) ----------------
__global__ void __launch_bounds__(256) dec_attn(const float* __restrict__ qt,
                                                const float* __restrict__ kc,
                                                const float* __restrict__ vc,
                                                float* __restrict__ ov, int kvlen)
{
    __shared__ float wts[CAP_];
    __shared__ float qs[64];
    __shared__ float red[8];
    __shared__ float part[256];
    __shared__ float sgmax, sgsum;
    const int h = blockIdx.x, b = blockIdx.y;
    const int tid = threadIdx.x;
    const int w = tid >> 5, lane = tid & 31;
    if (tid < 64) qs[tid] = qt[b * 512 + h * 64 + tid];
    __syncthreads();

    float lmax = -1e30f;
    for (int t = tid; t < kvlen; t += 256) {
        const float* kr = kc + ((size_t)b * CAP_ + t) * 512 + h * 64;
        float s = 0.f;
#pragma unroll
        for (int d = 0; d < 64; d += 4) {
            float4 kv = *(const float4*)(kr + d);
            s = fmaf(kv.x, qs[d], fmaf(kv.y, qs[d + 1],
                fmaf(kv.z, qs[d + 2], fmaf(kv.w, qs[d + 3], s))));
        }
        s *= 0.125f;
        wts[t] = s;
        lmax = fmaxf(lmax, s);
    }
    lmax = warpRedMax(lmax);
    if (lane == 0) red[w] = lmax;
    __syncthreads();
    if (tid == 0) {
        float m = red[0];
#pragma unroll
        for (int i = 1; i < 8; i++) m = fmaxf(m, red[i]);
        sgmax = m;
    }
    __syncthreads();
    const float gm = sgmax;
    float ls = 0.f;
    for (int t = tid; t < kvlen; t += 256) {
        float p = __expf(wts[t] - gm);
        wts[t] = p;
        ls += p;
    }
    ls = warpRedSum(ls);
    if (lane == 0) red[w] = ls;
    __syncthreads();
    if (tid == 0) {
        float ssum = 0.f;
#pragma unroll
        for (int i = 0; i < 8; i++) ssum += red[i];
        sgsum = ssum;
    }
    __syncthreads();
    const float inv = 1.f / sgsum;
    const int d = tid & 63, pt = tid >> 6;
    float acc = 0.f;
    for (int t = pt; t < kvlen; t += 4)
        acc = fmaf(wts[t], vc[((size_t)b * CAP_ + t) * 512 + h * 64 + d], acc);
    part[tid] = acc;
    __syncthreads();
    if (pt == 0)
        ov[b * 512 + h * 64 + d] =
            (part[d] + part[64 + d] + part[128 + d] + part[192 + d]) * inv;
}

// ---------------- decode: residual add + LayerNorm (512 threads per row) ----------------
__global__ void __launch_bounds__(512) dec_resid_ln(const float* __restrict__ acc,
                                                    const float* __restrict__ resid,
                                                    const float* __restrict__ g,
                                                    const float* __restrict__ be,
                                                    float* __restrict__ out,
                                                    size_t rowStride)
{
    const int b = blockIdx.x, n = threadIdx.x;
    float v = acc[b * 512 + n] + resid[b * 512 + n];
    __shared__ float r1[16], r2[16];
    __shared__ float smu, srs;
    float s  = warpRedSum(v);
    float s2 = warpRedSum(v * v);
    const int w = n >> 5, lane = n & 31;
    if (lane == 0) { r1[w] = s; r2[w] = s2; }
    __syncthreads();
    if (n == 0) {
        float S = 0.f, S2 = 0.f;
#pragma unroll
        for (int i = 0; i < 16; i++) { S += r1[i]; S2 += r2[i]; }
        float mu  = S * (1.f / 512.f);
        float var = S2 * (1.f / 512.f) - mu * mu;
        smu = mu; srs = rsqrtf(var + 1e-5f);
    }
    __syncthreads();
    out[(size_t)b * rowStride + n] = (v - smu) * srs * g[n] + be[n];
}

// ---------------- host launcher ----------------
struct ScratchPtrs {
    float *Qkv, *Attn, *Pre, *Hb, *Hff, *Kc, *Vc, *Qt, *At, *Ht, *Hfft, *T1;
};

static const ScratchPtrs& get_scratch() {
    static ScratchPtrs p;
    static bool init = false;
    if (!init) {
        cudaGetSymbolAddress((void**)&p.Qkv,  g_qkv);
        cudaGetSymbolAddress((void**)&p.Attn, g_attn);
        cudaGetSymbolAddress((void**)&p.Pre,  g_pre);
        cudaGetSymbolAddress((void**)&p.Hb,   g_h);
        cudaGetSymbolAddress((void**)&p.Hff,  g_hff);
        cudaGetSymbolAddress((void**)&p.Kc,   g_kc);
        cudaGetSymbolAddress((void**)&p.Vc,   g_vc);
        cudaGetSymbolAddress((void**)&p.Qt,   g_qt);
        cudaGetSymbolAddress((void**)&p.At,   g_at);
        cudaGetSymbolAddress((void**)&p.Ht,   g_ht);
        cudaGetSymbolAddress((void**)&p.Hfft, g_hfft);
        cudaGetSymbolAddress((void**)&p.T1,   g_t1);
        cudaFuncSetAttribute(attn_prefill,
                             cudaFuncAttributeMaxDynamicSharedMemorySize, 49408);
        init = true;
    }
    return p;
}

extern "C" void kernel_launch(void* const* d_in, const int* in_sizes, int n_in,
                              void* d_out, int out_size)
{
    (void)in_sizes; (void)n_in; (void)out_size;
    const float* x    = (const float*)d_in[0];
    const float* dx   = (const float*)d_in[1];
    // d_in[2] = causal_mask (bool) — unused, we compute causality analytically
    const float* qkvW = (const float*)d_in[3];
    const float* qkvB = (const float*)d_in[4];
    const float* outW = (const float*)d_in[5];
    const float* outB = (const float*)d_in[6];
    const float* w1   = (const float*)d_in[7];
    const float* b1   = (const float*)d_in[8];
    const float* w2   = (const float*)d_in[9];
    const float* b2   = (const float*)d_in[10];
    const float* ln1w = (const float*)d_in[11];
    const float* ln1b = (const float*)d_in[12];
    const float* ln2w = (const float*)d_in[13];
    const float* ln2b = (const float*)d_in[14];
    float* out = (float*)d_out;

    const ScratchPtrs& sp = get_scratch();

    // ---- prefill ----
    sgemm_nt<1,0,0><<<dim3(12, 64), 256>>>(x, qkvW, qkvB, nullptr, sp.Qkv, MTOK, 1536, 512);
    copy_kv<<<MTOK, 128>>>(sp.Qkv, sp.Kc, sp.Vc);
    attn_prefill<<<dim3(16, 64), 256, 49408>>>(sp.Qkv, sp.Attn);
    sgemm_nt<1,0,1><<<dim3(4, 64), 256>>>(sp.Attn, outW, outB, x, sp.Pre, MTOK, 512, 512);
    ln_rows<<<MTOK, 256>>>(sp.Pre, ln1w, ln1b, sp.Hb, 0);
    sgemm_nt<1,1,0><<<dim3(16, 64), 256>>>(sp.Hb, w1, b1, nullptr, sp.Hff, MTOK, 2048, 512);
    sgemm_nt<1,0,1><<<dim3(4, 64), 256>>>(sp.Hff, w2, b2, sp.Hb, sp.Pre, MTOK, 512, 2048);
    ln_rows<<<MTOK, 256>>>(sp.Pre, ln2w, ln2b, out, 64);  // row b*1024+s -> b*1088+s

    // ---- decode: 64 autoregressive steps ----
    for (int step = 0; step < STEPS_; step++) {
        const int cur = S_ + step;
        const float* xt = dx + (size_t)step * (B_ * D_);
        dec_qkv<<<dim3(192, 8), 256>>>(xt, qkvW, qkvB, sp.Qt, sp.Kc, sp.Vc, cur);
        dec_attn<<<dim3(8, 8), 256>>>(sp.Qt, sp.Kc, sp.Vc, sp.At, cur + 1);
        dec_gemv<<<dim3(64, 8), 256>>>(sp.At, outW, outB, sp.T1, 512, 512, 0);
        dec_resid_ln<<<8, 512>>>(sp.T1, xt, ln1w, ln1b, sp.Ht, 512);
        dec_gemv<<<dim3(256, 8), 256>>>(sp.Ht, w1, b1, sp.Hfft, 512, 2048, 1);
        dec_gemv<<<dim3(64, 8), 256>>>(sp.Hfft, w2, b2, sp.T1, 2048, 512, 0);
        dec_resid_ln<<<8, 512>>>(sp.T1, sp.Ht, ln2w, ln2b,
                                 out + (size_t)cur * 512, (size_t)CAP_ * 512);
    }
}

// round 2
// speedup vs baseline: 1.1319x; 1.1319x over previous
#include <cuda_runtime.h>
#include <cstdint>

#define B_     8
#define S_     1024
#define D_     512
#define H_     8
#define HD_    64
#define FF_    2048
#define STEPS_ 64
#define CAP_   1088
#define MTOK   (B_*S_)   /* 8192 */
#define NBLK   128

// ---------------- device scratch (no cudaMalloc allowed) ----------------
__device__ float g_qkv [MTOK*1536];   // prefill QKV
__device__ float g_attn[MTOK*D_];     // prefill attention output
__device__ float g_pre [MTOK*D_];     // pre-LN buffer
__device__ float g_h   [MTOK*D_];     // post-LN1 hidden
__device__ float g_hff [MTOK*FF_];    // MLP hidden
__device__ float g_kc  [B_*CAP_*D_];  // K cache
__device__ float g_vc  [B_*CAP_*D_];  // V cache
__device__ float g_qt  [B_*D_];       // decode q
__device__ float g_at  [B_*D_];       // decode attn out
__device__ float g_ht  [B_*D_];       // decode post-LN1
__device__ float g_hfft[B_*FF_];      // decode MLP hidden
__device__ float g_t1  [B_*D_];       // decode temp
__device__ unsigned g_bar_count;      // global barrier arrivals
__device__ unsigned g_bar_sense;      // global barrier release sense

// ---------------- reductions ----------------
__device__ __forceinline__ float warpRedSum(float v) {
#pragma unroll
    for (int o = 16; o; o >>= 1) v += __shfl_xor_sync(0xffffffffu, v, o);
    return v;
}
__device__ __forceinline__ float warpRedMax(float v) {
#pragma unroll
    for (int o = 16; o; o >>= 1) v = fmaxf(v, __shfl_xor_sync(0xffffffffu, v, o));
    return v;
}

// ---------------- global software barrier (all NBLK blocks co-resident) ----------------
__device__ __forceinline__ void gbar(unsigned& target, int tid) {
    __threadfence();
    __syncthreads();
    target += 1;
    if (tid == 0) {
        unsigned arrived = atomicAdd(&g_bar_count, 1u) + 1u;
        if (arrived == (unsigned)NBLK) {
            atomicExch(&g_bar_count, 0u);
            __threadfence();
            atomicExch(&g_bar_sense, target);
        } else {
            while (atomicAdd(&g_bar_sense, 0u) < target) { }
        }
    }
    __syncthreads();
    __threadfence();
}

// ---------------- SGEMM (NT): C[m,n] = sum_k A[m,k]*B[n,k] (+bias,+res,relu) ----------------
template<int BIAS, int RELU, int RES>
__global__ void __launch_bounds__(256) sgemm_nt(
    const float* __restrict__ A, const float* __restrict__ Bm,
    const float* __restrict__ bias, const float* __restrict__ R,
    float* __restrict__ C, int M, int N, int K)
{
    __shared__ float As[16][132];
    __shared__ float Bs[16][132];
    const int tid = threadIdx.x;
    const int m0 = blockIdx.y * 128;
    const int n0 = blockIdx.x * 128;
    const int tx = tid & 15, ty = tid >> 4;
    const int r0 = ty * 8, c0 = tx * 8;
    const int lrow = tid >> 2;
    const int lk4  = (tid & 3) * 4;

    float acc[8][8];
#pragma unroll
    for (int i = 0; i < 8; i++)
#pragma unroll
        for (int j = 0; j < 8; j++) acc[i][j] = 0.f;

    for (int k0 = 0; k0 < K; k0 += 16) {
#pragma unroll
        for (int half = 0; half < 2; half++) {
            int row = lrow + half * 64;
            float4 a = *(const float4*)(A + (size_t)(m0 + row) * K + k0 + lk4);
            As[lk4 + 0][row] = a.x; As[lk4 + 1][row] = a.y;
            As[lk4 + 2][row] = a.z; As[lk4 + 3][row] = a.w;
            float4 b = *(const float4*)(Bm + (size_t)(n0 + row) * K + k0 + lk4);
            Bs[lk4 + 0][row] = b.x; Bs[lk4 + 1][row] = b.y;
            Bs[lk4 + 2][row] = b.z; Bs[lk4 + 3][row] = b.w;
        }
        __syncthreads();
#pragma unroll
        for (int kk = 0; kk < 16; kk++) {
            float af[8], bf[8];
            *(float4*)(af)     = *(const float4*)(&As[kk][r0]);
            *(float4*)(af + 4) = *(const float4*)(&As[kk][r0 + 4]);
            *(float4*)(bf)     = *(const float4*)(&Bs[kk][c0]);
            *(float4*)(bf + 4) = *(const float4*)(&Bs[kk][c0 + 4]);
#pragma unroll
            for (int i = 0; i < 8; i++)
#pragma unroll
                for (int j = 0; j < 8; j++)
                    acc[i][j] = fmaf(af[i], bf[j], acc[i][j]);
        }
        __syncthreads();
    }

    float bl[8];
#pragma unroll
    for (int j = 0; j < 8; j++) bl[j] = BIAS ? bias[n0 + c0 + j] : 0.f;

#pragma unroll
    for (int i = 0; i < 8; i++) {
        size_t rowoff = (size_t)(m0 + r0 + i) * N + n0 + c0;
#pragma unroll
        for (int j4 = 0; j4 < 8; j4 += 4) {
            float t0 = acc[i][j4 + 0] + bl[j4 + 0];
            float t1 = acc[i][j4 + 1] + bl[j4 + 1];
            float t2 = acc[i][j4 + 2] + bl[j4 + 2];
            float t3 = acc[i][j4 + 3] + bl[j4 + 3];
            if (RES) {
                float4 r = *(const float4*)(R + rowoff + j4);
                t0 += r.x; t1 += r.y; t2 += r.z; t3 += r.w;
            }
            if (RELU) {
                t0 = fmaxf(t0, 0.f); t1 = fmaxf(t1, 0.f);
                t2 = fmaxf(t2, 0.f); t3 = fmaxf(t3, 0.f);
            }
            float4 v; v.x = t0; v.y = t1; v.z = t2; v.w = t3;
            *(float4*)(C + rowoff + j4) = v;
        }
    }
}

// ---------------- prefill flash attention (causal), 64x64 tiles ----------------
__global__ void __launch_bounds__(256) attn_prefill(const float* __restrict__ qkv,
                                                    float* __restrict__ attn)
{
    extern __shared__ float sm[];
    float* Qs = sm;
    float* KP = sm + 64 * 64;
    float* Vs = KP + 64 * 65;

    const int b  = blockIdx.y >> 3;
    const int h  = blockIdx.y & 7;
    const int l0 = blockIdx.x * 64;
    const int tid = threadIdx.x;
    const int tx = tid & 15, ty = tid >> 4;
    const int r0 = ty * 4, c0 = tx * 4;

    const size_t rowbase = (size_t)(b * S_) * 1536;
    const float* qbase = qkv + rowbase + h * 64;
    const float* kbase = qkv + rowbase + 512 + h * 64;
    const float* vbase = qkv + rowbase + 1024 + h * 64;

    const int lt  = tid >> 4;
    const int ld4 = (tid & 15) * 4;

#pragma unroll
    for (int tt = lt; tt < 64; tt += 16) {
        float4 q4 = *(const float4*)(qbase + (size_t)(l0 + tt) * 1536 + ld4);
        Qs[(ld4 + 0) * 64 + tt] = q4.x;
        Qs[(ld4 + 1) * 64 + tt] = q4.y;
        Qs[(ld4 + 2) * 64 + tt] = q4.z;
        Qs[(ld4 + 3) * 64 + tt] = q4.w;
    }

    float o[4][4];
    float mrow[4], lrow[4];
#pragma unroll
    for (int i = 0; i < 4; i++) {
        mrow[i] = -1e30f; lrow[i] = 0.f;
#pragma unroll
        for (int j = 0; j < 4; j++) o[i][j] = 0.f;
    }

    const int ntiles = (l0 >> 6) + 1;
    for (int tile = 0; tile < ntiles; ++tile) {
        const int j0 = tile * 64;
        __syncthreads();
#pragma unroll
        for (int tt = lt; tt < 64; tt += 16) {
            float4 k4 = *(const float4*)(kbase + (size_t)(j0 + tt) * 1536 + ld4);
            KP[(ld4 + 0) * 65 + tt] = k4.x;
            KP[(ld4 + 1) * 65 + tt] = k4.y;
            KP[(ld4 + 2) * 65 + tt] = k4.z;
            KP[(ld4 + 3) * 65 + tt] = k4.w;
            float4 v4 = *(const float4*)(vbase + (size_t)(j0 + tt) * 1536 + ld4);
            *(float4*)(Vs + tt * 64 + ld4) = v4;
        }
        __syncthreads();

        float s[4][4];
#pragma unroll
        for (int i = 0; i < 4; i++)
#pragma unroll
            for (int j = 0; j < 4; j++) s[i][j] = 0.f;

        for (int d = 0; d < 64; d++) {
            float qf[4];
            *(float4*)qf = *(const float4*)(Qs + d * 64 + r0);
            float kf0 = KP[d * 65 + c0 + 0];
            float kf1 = KP[d * 65 + c0 + 1];
            float kf2 = KP[d * 65 + c0 + 2];
            float kf3 = KP[d * 65 + c0 + 3];
#pragma unroll
            for (int i = 0; i < 4; i++) {
                s[i][0] = fmaf(qf[i], kf0, s[i][0]);
                s[i][1] = fmaf(qf[i], kf1, s[i][1]);
                s[i][2] = fmaf(qf[i], kf2, s[i][2]);
                s[i][3] = fmaf(qf[i], kf3, s[i][3]);
            }
        }

        if (j0 == l0) {
#pragma unroll
            for (int i = 0; i < 4; i++)
#pragma unroll
                for (int j = 0; j < 4; j++)
                    s[i][j] = (j0 + c0 + j > l0 + r0 + i) ? -1e30f : s[i][j] * 0.125f;
        } else {
#pragma unroll
            for (int i = 0; i < 4; i++)
#pragma unroll
                for (int j = 0; j < 4; j++) s[i][j] *= 0.125f;
        }

        float p[4][4];
#pragma unroll
        for (int i = 0; i < 4; i++) {
            float rm = fmaxf(fmaxf(s[i][0], s[i][1]), fmaxf(s[i][2], s[i][3]));
#pragma unroll
            for (int off = 8; off; off >>= 1)
                rm = fmaxf(rm, __shfl_xor_sync(0xffffffffu, rm, off));
            float mnew  = fmaxf(mrow[i], rm);
            float alpha = __expf(mrow[i] - mnew);
            float ps = 0.f;
#pragma unroll
            for (int j = 0; j < 4; j++) { p[i][j] = __expf(s[i][j] - mnew); ps += p[i][j]; }
#pragma unroll
            for (int off = 8; off; off >>= 1)
                ps += __shfl_xor_sync(0xffffffffu, ps, off);
            lrow[i] = lrow[i] * alpha + ps;
            mrow[i] = mnew;
#pragma unroll
            for (int j = 0; j < 4; j++) o[i][j] *= alpha;
        }

        __syncthreads();
#pragma unroll
        for (int i = 0; i < 4; i++)
#pragma unroll
            for (int j = 0; j < 4; j++)
                KP[(r0 + i) * 65 + c0 + j] = p[i][j];
        __syncthreads();

        for (int c = 0; c < 64; c++) {
            float vv[4];
            *(float4*)vv = *(const float4*)(Vs + c * 64 + c0);
            float p0 = KP[(r0 + 0) * 65 + c];
            float p1 = KP[(r0 + 1) * 65 + c];
            float p2 = KP[(r0 + 2) * 65 + c];
            float p3 = KP[(r0 + 3) * 65 + c];
#pragma unroll
            for (int j = 0; j < 4; j++) {
                o[0][j] = fmaf(p0, vv[j], o[0][j]);
                o[1][j] = fmaf(p1, vv[j], o[1][j]);
                o[2][j] = fmaf(p2, vv[j], o[2][j]);
                o[3][j] = fmaf(p3, vv[j], o[3][j]);
            }
        }
    }

    float* ob = attn + (size_t)(b * S_ + l0) * 512 + h * 64;
#pragma unroll
    for (int i = 0; i < 4; i++) {
        float inv = 1.f / lrow[i];
        float4 v;
        v.x = o[i][0] * inv; v.y = o[i][1] * inv;
        v.z = o[i][2] * inv; v.w = o[i][3] * inv;
        *(float4*)(ob + (size_t)(r0 + i) * 512 + c0) = v;
    }
}

// ---------------- copy prefill K/V slices into the caches ----------------
__global__ void __launch_bounds__(128) copy_kv(const float* __restrict__ qkv,
                                               float* __restrict__ kc, float* __restrict__ vc)
{
    const int r = blockIdx.x;
    const int b = r >> 10, s = r & 1023;
    const int tid = threadIdx.x;
    const float4* src = (const float4*)(qkv + (size_t)r * 1536);
    float4* kd = (float4*)(kc + (size_t)(b * CAP_ + s) * 512);
    float4* vd = (float4*)(vc + (size_t)(b * CAP_ + s) * 512);
    kd[tid] = src[128 + tid];
    vd[tid] = src[256 + tid];
}

// ---------------- prefill LayerNorm over rows of 512 ----------------
__global__ void __launch_bounds__(256) ln_rows(const float* __restrict__ in,
                                               const float* __restrict__ g,
                                               const float* __restrict__ be,
                                               float* __restrict__ out, int outExtra)
{
    const int r = blockIdx.x;
    const int tid = threadIdx.x;
    const float* row = in + (size_t)r * 512;
    float v0 = row[tid], v1 = row[tid + 256];
    float s  = warpRedSum(v0 + v1);
    float s2 = warpRedSum(v0 * v0 + v1 * v1);
    __shared__ float r1[8], r2[8];
    __shared__ float smu, srs;
    const int w = tid >> 5, lane = tid & 31;
    if (lane == 0) { r1[w] = s; r2[w] = s2; }
    __syncthreads();
    if (tid == 0) {
        float S = 0.f, S2 = 0.f;
#pragma unroll
        for (int i = 0; i < 8; i++) { S += r1[i]; S2 += r2[i]; }
        float mu  = S * (1.f / 512.f);
        float var = S2 * (1.f / 512.f) - mu * mu;
        smu = mu; srs = rsqrtf(var + 1e-5f);
    }
    __syncthreads();
    const int orow = r + (r >> 10) * outExtra;
    float* od = out + (size_t)orow * 512;
    od[tid]       = (v0 - smu) * srs * g[tid]       + be[tid];
    od[tid + 256] = (v1 - smu) * srs * g[tid + 256] + be[tid + 256];
}

// ---------------- megakernel building blocks ----------------
// 4-batch weight-stationary dot: one warp, one weight row, xs holds 4 rows [4][Kstride]
template<int KP>
__device__ __forceinline__ void dot4(const float* __restrict__ wr,
                                     const float* xs, int Kstride, int lane,
                                     float& a0, float& a1, float& a2, float& a3)
{
    a0 = a1 = a2 = a3 = 0.f;
#pragma unroll
    for (int kp = 0; kp < KP; kp++) {
        const int k4 = kp * 128 + lane * 4;
        float4 wv = *(const float4*)(wr + k4);
        float4 x0 = *(const float4*)(xs + k4);
        float4 x1 = *(const float4*)(xs + Kstride + k4);
        float4 x2 = *(const float4*)(xs + 2 * Kstride + k4);
        float4 x3 = *(const float4*)(xs + 3 * Kstride + k4);
        a0 = fmaf(wv.x, x0.x, fmaf(wv.y, x0.y, fmaf(wv.z, x0.z, fmaf(wv.w, x0.w, a0))));
        a1 = fmaf(wv.x, x1.x, fmaf(wv.y, x1.y, fmaf(wv.z, x1.z, fmaf(wv.w, x1.w, a1))));
        a2 = fmaf(wv.x, x2.x, fmaf(wv.y, x2.y, fmaf(wv.z, x2.z, fmaf(wv.w, x2.w, a2))));
        a3 = fmaf(wv.x, x3.x, fmaf(wv.y, x3.y, fmaf(wv.z, x3.z, fmaf(wv.w, x3.w, a3))));
    }
    a0 = warpRedSum(a0); a1 = warpRedSum(a1);
    a2 = warpRedSum(a2); a3 = warpRedSum(a3);
}

// in-block residual + LayerNorm over a 512-row (256 threads, 2 elems each)
__device__ __forceinline__ void block_ln(const float* __restrict__ a,
                                         const float* __restrict__ r,
                                         const float* __restrict__ gw,
                                         const float* __restrict__ gb,
                                         float* __restrict__ o,
                                         int tid, float* s_red)
{
    __syncthreads();
    float v0 = a[tid] + r[tid];
    float v1 = a[tid + 256] + r[tid + 256];
    float s  = warpRedSum(v0 + v1);
    float s2 = warpRedSum(v0 * v0 + v1 * v1);
    const int w = tid >> 5, lane = tid & 31;
    if (lane == 0) { s_red[w] = s; s_red[8 + w] = s2; }
    __syncthreads();
    float S = 0.f, S2 = 0.f;
#pragma unroll
    for (int i = 0; i < 8; i++) { S += s_red[i]; S2 += s_red[8 + i]; }
    float mu = S * (1.f / 512.f);
    float rs = rsqrtf(S2 * (1.f / 512.f) - mu * mu + 1e-5f);
    o[tid]       = (v0 - mu) * rs * gw[tid]       + gb[tid];
    o[tid + 256] = (v1 - mu) * rs * gw[tid + 256] + gb[tid + 256];
    __syncthreads();
}

// ---------------- decode megakernel: all 64 steps in one launch ----------------
// grid: 128 blocks x 256 threads (co-resident), dynamic smem = 32KB
__global__ void __launch_bounds__(256, 1) decode_mega(
    const float* __restrict__ dx,
    const float* __restrict__ qkvW, const float* __restrict__ qkvB,
    const float* __restrict__ outW, const float* __restrict__ outB,
    const float* __restrict__ w1, const float* __restrict__ b1,
    const float* __restrict__ w2, const float* __restrict__ b2,
    const float* __restrict__ ln1w, const float* __restrict__ ln1b,
    const float* __restrict__ ln2w, const float* __restrict__ ln2b,
    float* __restrict__ out,
    float* __restrict__ qt, float* __restrict__ kc, float* __restrict__ vc,
    float* __restrict__ at, float* __restrict__ ht,
    float* __restrict__ hfft, float* __restrict__ t1)
{
    extern __shared__ float xs[];      // 8192 floats (32KB)
    __shared__ float s_red[32];
    __shared__ float s_q[64];
    __shared__ float s_part[256];

    const int tid  = threadIdx.x;
    const int bid  = blockIdx.x;
    const int w    = tid >> 5, lane = tid & 31;
    const int half = bid >> 6;           // 0/1: which 4-batch group
    const int b0   = half * 4;
    const int wg   = (bid & 63) * 8 + w; // 0..511 warp-global index within half

    unsigned target = 0;
    if (tid == 0) target = atomicAdd(&g_bar_sense, 0u);

    for (int step = 0; step < STEPS_; step++) {
        const int cur = S_ + step;
        const float* xt = dx + (size_t)step * (B_ * D_);

        // ===== phase A: LN2(prev step) on blocks 0..7 + QKV(this step) on all =====
        if (step > 0 && bid < 8)
            block_ln(t1 + bid * 512, ht + bid * 512, ln2w, ln2b,
                     out + ((size_t)bid * CAP_ + (cur - 1)) * 512, tid, s_red);
        {
            const float4* src = (const float4*)xt + (size_t)b0 * 128;
            float4* d4 = (float4*)xs;
            for (int i = tid; i < 512; i += 256) d4[i] = src[i];
        }
        __syncthreads();
#pragma unroll
        for (int o = 0; o < 3; o++) {
            const int n = wg + o * 512;
            float a0, a1, a2, a3;
            dot4<4>(qkvW + (size_t)n * 512, xs, 512, lane, a0, a1, a2, a3);
            if (lane == 0) {
                const float bv = qkvB[n];
                if (o == 0) {
                    qt[(b0 + 0) * 512 + wg] = a0 + bv;
                    qt[(b0 + 1) * 512 + wg] = a1 + bv;
                    qt[(b0 + 2) * 512 + wg] = a2 + bv;
                    qt[(b0 + 3) * 512 + wg] = a3 + bv;
                } else if (o == 1) {
                    kc[((size_t)(b0 + 0) * CAP_ + cur) * 512 + wg] = a0 + bv;
                    kc[((size_t)(b0 + 1) * CAP_ + cur) * 512 + wg] = a1 + bv;
                    kc[((size_t)(b0 + 2) * CAP_ + cur) * 512 + wg] = a2 + bv;
                    kc[((size_t)(b0 + 3) * CAP_ + cur) * 512 + wg] = a3 + bv;
                } else {
                    vc[((size_t)(b0 + 0) * CAP_ + cur) * 512 + wg] = a0 + bv;
                    vc[((size_t)(b0 + 1) * CAP_ + cur) * 512 + wg] = a1 + bv;
                    vc[((size_t)(b0 + 2) * CAP_ + cur) * 512 + wg] = a2 + bv;
                    vc[((size_t)(b0 + 3) * CAP_ + cur) * 512 + wg] = a3 + bv;
                }
            }
        }
        gbar(target, tid);

        // ===== phase B: attention, blocks 0..63 = (h, b) =====
        if (bid < 64) {
            const int h = bid & 7, bb = bid >> 3;
            const int kvlen = cur + 1;
            if (tid < 64) s_q[tid] = qt[bb * 512 + h * 64 + tid];
            __syncthreads();
            // K-dot: 4 lanes per t-row (each lane 16 dims), 8 t per warp round
            const int tl = lane >> 2;
            const int kq = (lane & 3) * 16;
            const float4 qa = *(const float4*)(s_q + kq);
            const float4 qb = *(const float4*)(s_q + kq + 4);
            const float4 qc = *(const float4*)(s_q + kq + 8);
            const float4 qd = *(const float4*)(s_q + kq + 12);
            const float* kb = kc + (size_t)bb * CAP_ * 512 + h * 64;
            for (int t0 = 0; t0 < kvlen; t0 += 64) {
                const int t = t0 + w * 8 + tl;
                const bool valid = t < kvlen;
                const float* kr = kb + (size_t)(valid ? t : 0) * 512 + kq;
                float4 k0 = *(const float4*)(kr);
                float4 k1 = *(const float4*)(kr + 4);
                float4 k2 = *(const float4*)(kr + 8);
                float4 k3 = *(const float4*)(kr + 12);
                float s;
                s = k0.x * qa.x;
                s = fmaf(k0.y, qa.y, s); s = fmaf(k0.z, qa.z, s); s = fmaf(k0.w, qa.w, s);
                s = fmaf(k1.x, qb.x, s); s = fmaf(k1.y, qb.y, s);
                s = fmaf(k1.z, qb.z, s); s = fmaf(k1.w, qb.w, s);
                s = fmaf(k2.x, qc.x, s); s = fmaf(k2.y, qc.y, s);
                s = fmaf(k2.z, qc.z, s); s = fmaf(k2.w, qc.w, s);
                s = fmaf(k3.x, qd.x, s); s = fmaf(k3.y, qd.y, s);
                s = fmaf(k3.z, qd.z, s); s = fmaf(k3.w, qd.w, s);
                s += __shfl_xor_sync(0xffffffffu, s, 1);
                s += __shfl_xor_sync(0xffffffffu, s, 2);
                if (valid && (lane & 3) == 0) xs[t] = s * 0.125f;
            }
            __syncthreads();
            // softmax over xs[0..kvlen)
            float lmax = -1e30f;
            for (int t = tid; t < kvlen; t += 256) lmax = fmaxf(lmax, xs[t]);
            lmax = warpRedMax(lmax);
            if (lane == 0) s_red[w] = lmax;
            __syncthreads();
            float gm = s_red[0];
#pragma unroll
            for (int i = 1; i < 8; i++) gm = fmaxf(gm, s_red[i]);
            float ls = 0.f;
            for (int t = tid; t < kvlen; t += 256) {
                float p = __expf(xs[t] - gm);
                xs[t] = p;
                ls += p;
            }
            ls = warpRedSum(ls);
            if (lane == 0) s_red[8 + w] = ls;
            __syncthreads();
            float ssum = 0.f;
#pragma unroll
            for (int i = 0; i < 8; i++) ssum += s_red[8 + i];
            const float inv = 1.f / ssum;
            // V accumulate: 4 groups x 64 dims
            const int d = tid & 63, pt = tid >> 6;
            const float* vb = vc + (size_t)bb * CAP_ * 512 + h * 64 + d;
            float acc = 0.f;
            for (int t = pt; t < kvlen; t += 4)
                acc = fmaf(xs[t], vb[(size_t)t * 512], acc);
            s_part[tid] = acc;
            __syncthreads();
            if (pt == 0)
                at[bb * 512 + h * 64 + d] =
                    (s_part[d] + s_part[64 + d] + s_part[128 + d] + s_part[192 + d]) * inv;
        }
        gbar(target, tid);

        // ===== phase C: out-projection (N=512, K=512) -> t1 =====
        {
            const float4* src = (const float4*)at + (size_t)b0 * 128;
            float4* d4 = (float4*)xs;
            for (int i = tid; i < 512; i += 256) d4[i] = src[i];
        }
        __syncthreads();
        {
            float a0, a1, a2, a3;
            dot4<4>(outW + (size_t)wg * 512, xs, 512, lane, a0, a1, a2, a3);
            if (lane == 0) {
                const float bv = outB[wg];
                t1[(b0 + 0) * 512 + wg] = a0 + bv;
                t1[(b0 + 1) * 512 + wg] = a1 + bv;
                t1[(b0 + 2) * 512 + wg] = a2 + bv;
                t1[(b0 + 3) * 512 + wg] = a3 + bv;
            }
        }
        gbar(target, tid);

        // ===== phase D: residual + LN1 -> ht (blocks 0..7) =====
        if (bid < 8)
            block_ln(t1 + bid * 512, xt + bid * 512, ln1w, ln1b,
                     ht + bid * 512, tid, s_red);
        gbar(target, tid);

        // ===== phase E: FF1 (N=2048, K=512, relu) -> hfft =====
        {
            const float4* src = (const float4*)ht + (size_t)b0 * 128;
            float4* d4 = (float4*)xs;
            for (int i = tid; i < 512; i += 256) d4[i] = src[i];
        }
        __syncthreads();
#pragma unroll
        for (int o = 0; o < 4; o++) {
            const int n = wg + o * 512;
            float a0, a1, a2, a3;
            dot4<4>(w1 + (size_t)n * 512, xs, 512, lane, a0, a1, a2, a3);
            if (lane == 0) {
                const float bv = b1[n];
                hfft[(b0 + 0) * 2048 + n] = fmaxf(a0 + bv, 0.f);
                hfft[(b0 + 1) * 2048 + n] = fmaxf(a1 + bv, 0.f);
                hfft[(b0 + 2) * 2048 + n] = fmaxf(a2 + bv, 0.f);
                hfft[(b0 + 3) * 2048 + n] = fmaxf(a3 + bv, 0.f);
            }
        }
        gbar(target, tid);

        // ===== phase F: FF2 (N=512, K=2048) -> t1 =====
        {
            const float4* src = (const float4*)hfft + (size_t)b0 * 512;
            float4* d4 = (float4*)xs;
            for (int i = tid; i < 2048; i += 256) d4[i] = src[i];
        }
        __syncthreads();
        {
            float a0, a1, a2, a3;
            dot4<16>(w2 + (size_t)wg * 2048, xs, 2048, lane, a0, a1, a2, a3);
            if (lane == 0) {
                const float bv = b2[wg];
                t1[(b0 + 0) * 512 + wg] = a0 + bv;
                t1[(b0 + 1) * 512 + wg] = a1 + bv;
                t1[(b0 + 2) * 512 + wg] = a2 + bv;
                t1[(b0 + 3) * 512 + wg] = a3 + bv;
            }
        }
        gbar(target, tid);
    }

    // final LN2 for the last step
    if (bid < 8)
        block_ln(t1 + bid * 512, ht + bid * 512, ln2w, ln2b,
                 out + ((size_t)bid * CAP_ + (S_ + STEPS_ - 1)) * 512, tid, s_red);
}

// ---------------- host launcher ----------------
struct ScratchPtrs {
    float *Qkv, *Attn, *Pre, *Hb, *Hff, *Kc, *Vc, *Qt, *At, *Ht, *Hfft, *T1;
};

static const ScratchPtrs& get_scratch() {
    static ScratchPtrs p;
    static bool init = false;
    if (!init) {
        cudaGetSymbolAddress((void**)&p.Qkv,  g_qkv);
        cudaGetSymbolAddress((void**)&p.Attn, g_attn);
        cudaGetSymbolAddress((void**)&p.Pre,  g_pre);
        cudaGetSymbolAddress((void**)&p.Hb,   g_h);
        cudaGetSymbolAddress((void**)&p.Hff,  g_hff);
        cudaGetSymbolAddress((void**)&p.Kc,   g_kc);
        cudaGetSymbolAddress((void**)&p.Vc,   g_vc);
        cudaGetSymbolAddress((void**)&p.Qt,   g_qt);
        cudaGetSymbolAddress((void**)&p.At,   g_at);
        cudaGetSymbolAddress((void**)&p.Ht,   g_ht);
        cudaGetSymbolAddress((void**)&p.Hfft, g_hfft);
        cudaGetSymbolAddress((void**)&p.T1,   g_t1);
        cudaFuncSetAttribute(attn_prefill,
                             cudaFuncAttributeMaxDynamicSharedMemorySize, 49408);
        init = true;
    }
    return p;
}

extern "C" void kernel_launch(void* const* d_in, const int* in_sizes, int n_in,
                              void* d_out, int out_size)
{
    (void)in_sizes; (void)n_in; (void)out_size;
    const float* x    = (const float*)d_in[0];
    const float* dx   = (const float*)d_in[1];
    // d_in[2] = causal_mask (bool) — unused, causality computed analytically
    const float* qkvW = (const float*)d_in[3];
    const float* qkvB = (const float*)d_in[4];
    const float* outW = (const float*)d_in[5];
    const float* outB = (const float*)d_in[6];
    const float* w1   = (const float*)d_in[7];
    const float* b1   = (const float*)d_in[8];
    const float* w2   = (const float*)d_in[9];
    const float* b2   = (const float*)d_in[10];
    const float* ln1w = (const float*)d_in[11];
    const float* ln1b = (const float*)d_in[12];
    const float* ln2w = (const float*)d_in[13];
    const float* ln2b = (const float*)d_in[14];
    float* out = (float*)d_out;

    const ScratchPtrs& sp = get_scratch();

    // ---- prefill ----
    sgemm_nt<1,0,0><<<dim3(12, 64), 256>>>(x, qkvW, qkvB, nullptr, sp.Qkv, MTOK, 1536, 512);
    copy_kv<<<MTOK, 128>>>(sp.Qkv, sp.Kc, sp.Vc);
    attn_prefill<<<dim3(16, 64), 256, 49408>>>(sp.Qkv, sp.Attn);
    sgemm_nt<1,0,1><<<dim3(4, 64), 256>>>(sp.Attn, outW, outB, x, sp.Pre, MTOK, 512, 512);
    ln_rows<<<MTOK, 256>>>(sp.Pre, ln1w, ln1b, sp.Hb, 0);
    sgemm_nt<1,1,0><<<dim3(16, 64), 256>>>(sp.Hb, w1, b1, nullptr, sp.Hff, MTOK, 2048, 512);
    sgemm_nt<1,0,1><<<dim3(4, 64), 256>>>(sp.Hff, w2, b2, sp.Hb, sp.Pre, MTOK, 512, 2048);
    ln_rows<<<MTOK, 256>>>(sp.Pre, ln2w, ln2b, out, 64);

    // ---- decode: all 64 steps in one persistent launch ----
    decode_mega<<<NBLK, 256, 32768>>>(dx, qkvW, qkvB, outW, outB,
                                      w1, b1, w2, b2,
                                      ln1w, ln1b, ln2w, ln2b, out,
                                      sp.Qt, sp.Kc, sp.Vc, sp.At, sp.Ht,
                                      sp.Hfft, sp.T1);
}